// round 2
// baseline (speedup 1.0000x reference)
#include <cuda_runtime.h>
#include <math.h>

#define N_NODES 100000
#define N_EDGES 800000
#define IN_FEATS 128
#define HID 64
#define SCALE 0.70710678118654752440f
#define BN_EPS 1e-5f

// ---------------- scratch (__device__ globals; no allocation allowed) -------
__device__ float g_h[N_NODES * HID];     // running hidden state
__device__ float g_t[N_NODES * HID];     // h @ w (per-layer temp)
__device__ float g_agg[N_NODES * HID];   // scatter accumulator
__device__ float g_norm_out[N_NODES];    // deg_out^-1/2
__device__ float g_norm_in[N_NODES];     // deg_in^-1/2
__device__ int   g_deg_out[N_NODES];
__device__ int   g_deg_in[N_NODES];
__device__ float g_sum[HID];
__device__ float g_sumsq[HID];
__device__ float g_mu[HID];
__device__ float g_rstd[HID];

// ---------------- kernels ---------------------------------------------------

__global__ void zero_misc_kernel() {
    int i = blockIdx.x * blockDim.x + threadIdx.x;
    if (i < N_NODES) { g_deg_out[i] = 0; g_deg_in[i] = 0; }
    if (i < HID)     { g_sum[i] = 0.f; g_sumsq[i] = 0.f; }
}

__global__ void degree_kernel(const int* __restrict__ src, const int* __restrict__ dst) {
    int e = blockIdx.x * blockDim.x + threadIdx.x;
    if (e >= N_EDGES) return;
    atomicAdd(&g_deg_out[src[e]], 1);
    atomicAdd(&g_deg_in[dst[e]], 1);
}

__global__ void norm_kernel() {
    int n = blockIdx.x * blockDim.x + threadIdx.x;
    if (n >= N_NODES) return;
    float dout = (float)max(g_deg_out[n], 1);
    float din  = (float)max(g_deg_in[n], 1);
    g_norm_out[n] = rsqrtf(dout);
    g_norm_in[n]  = rsqrtf(din);
}

// h = x @ fc_w + fc_b   (x: [N,128], fc_w: [128,64]) -- 4 rows per 256-thr block
__global__ void fc_kernel(const float* __restrict__ x,
                          const float* __restrict__ w,
                          const float* __restrict__ b) {
    __shared__ float ws[IN_FEATS * HID];   // 32 KB
    __shared__ float xs[4][IN_FEATS];      // 2 KB
    int tid = threadIdx.x;                  // 256 threads
    for (int i = tid; i < IN_FEATS * HID; i += 256) ws[i] = w[i];
    int row0 = blockIdx.x * 4;
    for (int i = tid; i < 4 * IN_FEATS; i += 256) {
        int r = i >> 7, k = i & 127;
        int node = row0 + r;
        xs[r][k] = (node < N_NODES) ? x[node * IN_FEATS + k] : 0.f;
    }
    __syncthreads();
    int j = tid & 63;       // output feature
    int r = tid >> 6;       // local row
    int node = row0 + r;
    if (node < N_NODES) {
        float acc = b[j];
        #pragma unroll 16
        for (int k = 0; k < IN_FEATS; k++)
            acc = fmaf(xs[r][k], ws[k * HID + j], acc);
        g_h[node * HID + j] = acc;
    }
}

// t = h @ w   (w: [64,64]) -- 4 rows per 256-thr block
__global__ void gemm64_kernel(const float* __restrict__ w) {
    __shared__ float ws[HID * HID];        // 16 KB
    __shared__ float xs[4][HID];
    int tid = threadIdx.x;                  // 256 threads
    for (int i = tid; i < HID * HID; i += 256) ws[i] = w[i];
    int row0 = blockIdx.x * 4;
    for (int i = tid; i < 4 * HID; i += 256) {
        int r = i >> 6, k = i & 63;
        int node = row0 + r;
        xs[r][k] = (node < N_NODES) ? g_h[node * HID + k] : 0.f;
    }
    __syncthreads();
    int j = tid & 63;
    int r = tid >> 6;
    int node = row0 + r;
    if (node < N_NODES) {
        float acc = 0.f;
        #pragma unroll 16
        for (int k = 0; k < HID; k++)
            acc = fmaf(xs[r][k], ws[k * HID + j], acc);
        g_t[node * HID + j] = acc;
    }
}

__global__ void zero_agg_kernel() {
    int i = blockIdx.x * blockDim.x + threadIdx.x;
    if (i < N_NODES * HID) g_agg[i] = 0.f;
}

// one warp per edge: agg[dst] += t[src] * norm_out[src]
__global__ void scatter_kernel(const int* __restrict__ src, const int* __restrict__ dst) {
    int warp = (blockIdx.x * blockDim.x + threadIdx.x) >> 5;
    int lane = threadIdx.x & 31;
    if (warp >= N_EDGES) return;
    int s = src[warp];
    int d = dst[warp];
    float ns = g_norm_out[s];
    float v0 = g_t[s * HID + lane]      * ns;
    float v1 = g_t[s * HID + 32 + lane] * ns;
    atomicAdd(&g_agg[d * HID + lane],      v0);
    atomicAdd(&g_agg[d * HID + 32 + lane], v1);
}

// h = (h + agg * norm_in[n] + b) * SCALE
__global__ void combine_kernel(const float* __restrict__ b) {
    int i = blockIdx.x * blockDim.x + threadIdx.x;
    if (i >= N_NODES * HID) return;
    int n = i >> 6;
    int j = i & 63;
    float v = g_h[i] + g_agg[i] * g_norm_in[n] + b[j];
    g_h[i] = v * SCALE;
}

// ---- BatchNorm (two-pass for accuracy) ----
__global__ void bn_sum_kernel() {
    int j = threadIdx.x;     // 64 threads
    float s = 0.f;
    for (int n = blockIdx.x; n < N_NODES; n += gridDim.x)
        s += g_h[n * HID + j];
    atomicAdd(&g_sum[j], s);
}

__global__ void bn_mu_kernel() {
    int j = threadIdx.x;
    if (j < HID) g_mu[j] = g_sum[j] / (float)N_NODES;
}

__global__ void bn_var_kernel() {
    int j = threadIdx.x;
    float mu = g_mu[j];
    float s = 0.f;
    for (int n = blockIdx.x; n < N_NODES; n += gridDim.x) {
        float d = g_h[n * HID + j] - mu;
        s += d * d;
    }
    atomicAdd(&g_sumsq[j], s);
}

__global__ void bn_rstd_kernel() {
    int j = threadIdx.x;
    if (j < HID) g_rstd[j] = rsqrtf(g_sumsq[j] / (float)N_NODES + BN_EPS);
}

__global__ void bn_apply_kernel(const float* __restrict__ gamma,
                                const float* __restrict__ beta,
                                float* __restrict__ out) {
    int i = blockIdx.x * blockDim.x + threadIdx.x;
    if (i >= N_NODES * HID) return;
    int j = i & 63;
    out[i] = (g_h[i] - g_mu[j]) * g_rstd[j] * gamma[j] + beta[j];
}

// ---------------- launch ----------------------------------------------------
extern "C" void kernel_launch(void* const* d_in, const int* in_sizes, int n_in,
                              void* d_out, int out_size) {
    const int*   src   = (const int*)  d_in[0];
    const int*   dst   = (const int*)  d_in[1];
    const float* x     = (const float*)d_in[2];
    const float* fc_w  = (const float*)d_in[3];
    const float* fc_b  = (const float*)d_in[4];
    const float* w1    = (const float*)d_in[5];
    const float* b1    = (const float*)d_in[6];
    const float* w2    = (const float*)d_in[7];
    const float* b2    = (const float*)d_in[8];
    const float* gamma = (const float*)d_in[9];
    const float* beta  = (const float*)d_in[10];
    float* out = (float*)d_out;

    const int NH = N_NODES * HID;

    // degrees + norms
    zero_misc_kernel<<<(N_NODES + 255) / 256, 256>>>();
    degree_kernel<<<(N_EDGES + 255) / 256, 256>>>(src, dst);
    norm_kernel<<<(N_NODES + 255) / 256, 256>>>();

    // fc
    fc_kernel<<<(N_NODES + 3) / 4, 256>>>(x, fc_w, fc_b);

    // layer 1
    gemm64_kernel<<<(N_NODES + 3) / 4, 256>>>(w1);
    zero_agg_kernel<<<(NH + 255) / 256, 256>>>();
    scatter_kernel<<<(N_EDGES * 32 + 255) / 256, 256>>>(src, dst);
    combine_kernel<<<(NH + 255) / 256, 256>>>(b1);

    // layer 2
    gemm64_kernel<<<(N_NODES + 3) / 4, 256>>>(w2);
    zero_agg_kernel<<<(NH + 255) / 256, 256>>>();
    scatter_kernel<<<(N_EDGES * 32 + 255) / 256, 256>>>(src, dst);
    combine_kernel<<<(NH + 255) / 256, 256>>>(b2);

    // batchnorm
    bn_sum_kernel<<<512, 64>>>();
    bn_mu_kernel<<<1, 64>>>();
    bn_var_kernel<<<512, 64>>>();
    bn_rstd_kernel<<<1, 64>>>();
    bn_apply_kernel<<<(NH + 255) / 256, 256>>>(gamma, beta, out);
}

// round 4
// speedup vs baseline: 4.1177x; 4.1177x over previous
#include <cuda_runtime.h>
#include <math.h>

#define N_NODES 100000
#define N_EDGES 800000
#define IN_FEATS 128
#define HID 64
#define NH (N_NODES * HID)
#define NH4 (NH / 4)
#define SCALE 0.70710678118654752440f
#define BN_EPS 1e-5f

// ---------------- scratch (__device__ globals; no allocation allowed) -------
__device__ float g_h[NH];
__device__ float g_t[NH];
__device__ float g_agg[NH];
__device__ float g_norm_out[N_NODES];
__device__ float g_norm_in[N_NODES];
__device__ int   g_deg_out[N_NODES];
__device__ int   g_deg_in[N_NODES];
__device__ float g_sum[HID];
__device__ float g_sumsq[HID];
__device__ float g_mu[HID];
__device__ float g_rstd[HID];

// ---------------- small kernels ---------------------------------------------

__global__ void zero_misc_kernel() {
    int i = blockIdx.x * blockDim.x + threadIdx.x;
    if (i < N_NODES) { g_deg_out[i] = 0; g_deg_in[i] = 0; }
    if (i < HID)     { g_sum[i] = 0.f; g_sumsq[i] = 0.f; }
}

__global__ void degree_kernel(const int* __restrict__ src, const int* __restrict__ dst) {
    int e = blockIdx.x * blockDim.x + threadIdx.x;
    if (e >= N_EDGES) return;
    atomicAdd(&g_deg_out[src[e]], 1);
    atomicAdd(&g_deg_in[dst[e]], 1);
}

__global__ void norm_kernel() {
    int n = blockIdx.x * blockDim.x + threadIdx.x;
    if (n >= N_NODES) return;
    g_norm_out[n] = rsqrtf((float)max(g_deg_out[n], 1));
    g_norm_in[n]  = rsqrtf((float)max(g_deg_in[n], 1));
}

__global__ void zero_agg_kernel() {
    int i = blockIdx.x * blockDim.x + threadIdx.x;
    if (i < NH4) ((float4*)g_agg)[i] = make_float4(0.f, 0.f, 0.f, 0.f);
}

// ---------------- register-tiled GEMMs ---------------------------------------
// 64x64 output tile / 256-thread block, 4x4 accumulators per thread.

// h = x @ fc_w + fc_b   (x: [N,128], fc_w: [128,64])
__global__ __launch_bounds__(256) void fc_kernel(const float* __restrict__ x,
                                                 const float* __restrict__ w,
                                                 const float* __restrict__ b) {
    __shared__ float xs[64][68];   // padded: avoid bank conflicts on column reads
    __shared__ float ws[64][64];
    int tid = threadIdx.x;
    int row0 = blockIdx.x * 64;
    int tx = tid & 15;             // 4-col group
    int ty = tid >> 4;             // 4-row group
    int r0 = ty * 4;

    float acc[4][4];
    #pragma unroll
    for (int i = 0; i < 4; i++)
        #pragma unroll
        for (int j = 0; j < 4; j++) acc[i][j] = 0.f;

    for (int kc = 0; kc < IN_FEATS; kc += 64) {
        for (int i = tid; i < 1024; i += 256) {          // ws chunk: 64x64
            int k = i >> 4, j4 = i & 15;
            ((float4*)&ws[k][0])[j4] = ((const float4*)(w + (size_t)(kc + k) * HID))[j4];
        }
        for (int i = tid; i < 1024; i += 256) {          // xs chunk: 64x64
            int r = i >> 4, k4 = i & 15;
            int node = row0 + r;
            float4 v = make_float4(0.f, 0.f, 0.f, 0.f);
            if (node < N_NODES) v = ((const float4*)(x + (size_t)node * IN_FEATS + kc))[k4];
            ((float4*)&xs[r][0])[k4] = v;
        }
        __syncthreads();
        #pragma unroll 16
        for (int k = 0; k < 64; k++) {
            float4 bv = ((float4*)&ws[k][0])[tx];
            float a0 = xs[r0 + 0][k];
            float a1 = xs[r0 + 1][k];
            float a2 = xs[r0 + 2][k];
            float a3 = xs[r0 + 3][k];
            acc[0][0] = fmaf(a0, bv.x, acc[0][0]); acc[0][1] = fmaf(a0, bv.y, acc[0][1]);
            acc[0][2] = fmaf(a0, bv.z, acc[0][2]); acc[0][3] = fmaf(a0, bv.w, acc[0][3]);
            acc[1][0] = fmaf(a1, bv.x, acc[1][0]); acc[1][1] = fmaf(a1, bv.y, acc[1][1]);
            acc[1][2] = fmaf(a1, bv.z, acc[1][2]); acc[1][3] = fmaf(a1, bv.w, acc[1][3]);
            acc[2][0] = fmaf(a2, bv.x, acc[2][0]); acc[2][1] = fmaf(a2, bv.y, acc[2][1]);
            acc[2][2] = fmaf(a2, bv.z, acc[2][2]); acc[2][3] = fmaf(a2, bv.w, acc[2][3]);
            acc[3][0] = fmaf(a3, bv.x, acc[3][0]); acc[3][1] = fmaf(a3, bv.y, acc[3][1]);
            acc[3][2] = fmaf(a3, bv.z, acc[3][2]); acc[3][3] = fmaf(a3, bv.w, acc[3][3]);
        }
        __syncthreads();
    }
    float4 bias = ((const float4*)b)[tx];
    #pragma unroll
    for (int i = 0; i < 4; i++) {
        int node = row0 + r0 + i;
        if (node < N_NODES) {
            float4 o;
            o.x = acc[i][0] + bias.x; o.y = acc[i][1] + bias.y;
            o.z = acc[i][2] + bias.z; o.w = acc[i][3] + bias.w;
            ((float4*)(g_h + (size_t)node * HID))[tx] = o;
        }
    }
}

// t = h @ w   (w: [64,64])
__global__ __launch_bounds__(256) void gemm64_kernel(const float* __restrict__ w) {
    __shared__ float xs[64][68];
    __shared__ float ws[64][64];
    int tid = threadIdx.x;
    int row0 = blockIdx.x * 64;
    int tx = tid & 15;
    int ty = tid >> 4;
    int r0 = ty * 4;

    for (int i = tid; i < 1024; i += 256) {
        int k = i >> 4, j4 = i & 15;
        ((float4*)&ws[k][0])[j4] = ((const float4*)(w + (size_t)k * HID))[j4];
    }
    for (int i = tid; i < 1024; i += 256) {
        int r = i >> 4, k4 = i & 15;
        int node = row0 + r;
        float4 v = make_float4(0.f, 0.f, 0.f, 0.f);
        if (node < N_NODES) v = ((const float4*)(g_h + (size_t)node * HID))[k4];
        ((float4*)&xs[r][0])[k4] = v;
    }
    __syncthreads();

    float acc[4][4];
    #pragma unroll
    for (int i = 0; i < 4; i++)
        #pragma unroll
        for (int j = 0; j < 4; j++) acc[i][j] = 0.f;

    #pragma unroll 16
    for (int k = 0; k < 64; k++) {
        float4 bv = ((float4*)&ws[k][0])[tx];
        float a0 = xs[r0 + 0][k];
        float a1 = xs[r0 + 1][k];
        float a2 = xs[r0 + 2][k];
        float a3 = xs[r0 + 3][k];
        acc[0][0] = fmaf(a0, bv.x, acc[0][0]); acc[0][1] = fmaf(a0, bv.y, acc[0][1]);
        acc[0][2] = fmaf(a0, bv.z, acc[0][2]); acc[0][3] = fmaf(a0, bv.w, acc[0][3]);
        acc[1][0] = fmaf(a1, bv.x, acc[1][0]); acc[1][1] = fmaf(a1, bv.y, acc[1][1]);
        acc[1][2] = fmaf(a1, bv.z, acc[1][2]); acc[1][3] = fmaf(a1, bv.w, acc[1][3]);
        acc[2][0] = fmaf(a2, bv.x, acc[2][0]); acc[2][1] = fmaf(a2, bv.y, acc[2][1]);
        acc[2][2] = fmaf(a2, bv.z, acc[2][2]); acc[2][3] = fmaf(a2, bv.w, acc[2][3]);
        acc[3][0] = fmaf(a3, bv.x, acc[3][0]); acc[3][1] = fmaf(a3, bv.y, acc[3][1]);
        acc[3][2] = fmaf(a3, bv.z, acc[3][2]); acc[3][3] = fmaf(a3, bv.w, acc[3][3]);
    }
    #pragma unroll
    for (int i = 0; i < 4; i++) {
        int node = row0 + r0 + i;
        if (node < N_NODES) {
            float4 o = make_float4(acc[i][0], acc[i][1], acc[i][2], acc[i][3]);
            ((float4*)(g_t + (size_t)node * HID))[tx] = o;
        }
    }
}

// ---------------- scatter: 16 lanes per edge, vectorized reductions ----------
__global__ void scatter_kernel(const int* __restrict__ src, const int* __restrict__ dst) {
    int gtid = blockIdx.x * blockDim.x + threadIdx.x;
    int e = gtid >> 4;
    if (e >= N_EDGES) return;
    int g = gtid & 15;
    int s = __ldg(src + e);
    int d = __ldg(dst + e);
    float ns = g_norm_out[s];
    float4 v = ((const float4*)(g_t + (size_t)s * HID))[g];
    float* p = g_agg + (size_t)d * HID + g * 4;
    asm volatile("red.global.add.v4.f32 [%0], {%1, %2, %3, %4};"
                 :: "l"(p), "f"(v.x * ns), "f"(v.y * ns), "f"(v.z * ns), "f"(v.w * ns)
                 : "memory");
}

// ---------------- combine layers ---------------------------------------------
// layer 1: h = (h + agg * norm_in + b) * SCALE
__global__ void combine_kernel(const float* __restrict__ b) {
    int i = blockIdx.x * blockDim.x + threadIdx.x;   // float4 index
    if (i >= NH4) return;
    int n = i >> 4;
    int j4 = i & 15;
    float ni = g_norm_in[n];
    float4 h = ((float4*)g_h)[i];
    float4 a = ((float4*)g_agg)[i];
    float4 bb = ((const float4*)b)[j4];
    h.x = (h.x + a.x * ni + bb.x) * SCALE;
    h.y = (h.y + a.y * ni + bb.y) * SCALE;
    h.z = (h.z + a.z * ni + bb.z) * SCALE;
    h.w = (h.w + a.w * ni + bb.w) * SCALE;
    ((float4*)g_h)[i] = h;
}

// layer 2 combine fused with BN statistics (sum and sum-of-squares).
// Grid-stride with stride % 16 == 0 so each thread keeps a fixed 4-feature group.
__global__ __launch_bounds__(256) void combine2_bn_kernel(const float* __restrict__ b) {
    __shared__ float ssum[HID];
    __shared__ float ssq[HID];
    int tid = threadIdx.x;
    if (tid < HID) { ssum[tid] = 0.f; ssq[tid] = 0.f; }
    __syncthreads();

    int start = blockIdx.x * 256 + tid;
    int j4 = start & 15;
    float4 bb = ((const float4*)b)[j4];
    float4 s4 = make_float4(0.f, 0.f, 0.f, 0.f);
    float4 q4 = make_float4(0.f, 0.f, 0.f, 0.f);

    int stride = gridDim.x * 256;   // multiple of 16 -> j4 invariant
    for (int i = start; i < NH4; i += stride) {
        int n = i >> 4;
        float ni = g_norm_in[n];
        float4 h = ((float4*)g_h)[i];
        float4 a = ((float4*)g_agg)[i];
        h.x = (h.x + a.x * ni + bb.x) * SCALE;
        h.y = (h.y + a.y * ni + bb.y) * SCALE;
        h.z = (h.z + a.z * ni + bb.z) * SCALE;
        h.w = (h.w + a.w * ni + bb.w) * SCALE;
        ((float4*)g_h)[i] = h;
        s4.x += h.x; s4.y += h.y; s4.z += h.z; s4.w += h.w;
        q4.x = fmaf(h.x, h.x, q4.x); q4.y = fmaf(h.y, h.y, q4.y);
        q4.z = fmaf(h.z, h.z, q4.z); q4.w = fmaf(h.w, h.w, q4.w);
    }
    int f = j4 * 4;
    atomicAdd(&ssum[f + 0], s4.x); atomicAdd(&ssum[f + 1], s4.y);
    atomicAdd(&ssum[f + 2], s4.z); atomicAdd(&ssum[f + 3], s4.w);
    atomicAdd(&ssq[f + 0], q4.x); atomicAdd(&ssq[f + 1], q4.y);
    atomicAdd(&ssq[f + 2], q4.z); atomicAdd(&ssq[f + 3], q4.w);
    __syncthreads();
    if (tid < HID) {
        atomicAdd(&g_sum[tid], ssum[tid]);
        atomicAdd(&g_sumsq[tid], ssq[tid]);
    }
}

__global__ void bn_finalize_kernel() {
    int j = threadIdx.x;
    if (j < HID) {
        float mu = g_sum[j] / (float)N_NODES;
        float var = g_sumsq[j] / (float)N_NODES - mu * mu;
        g_mu[j] = mu;
        g_rstd[j] = rsqrtf(var + BN_EPS);
    }
}

__global__ void bn_apply_kernel(const float* __restrict__ gamma,
                                const float* __restrict__ beta,
                                float* __restrict__ out) {
    int i = blockIdx.x * blockDim.x + threadIdx.x;   // float4 index
    if (i >= NH4) return;
    int j4 = i & 15;
    float4 h  = ((float4*)g_h)[i];
    float4 mu = ((float4*)g_mu)[j4];
    float4 rs = ((float4*)g_rstd)[j4];
    float4 ga = ((const float4*)gamma)[j4];
    float4 be = ((const float4*)beta)[j4];
    float4 o;
    o.x = (h.x - mu.x) * rs.x * ga.x + be.x;
    o.y = (h.y - mu.y) * rs.y * ga.y + be.y;
    o.z = (h.z - mu.z) * rs.z * ga.z + be.z;
    o.w = (h.w - mu.w) * rs.w * ga.w + be.w;
    ((float4*)out)[i] = o;
}

// ---------------- launch ------------------------------------------------------
extern "C" void kernel_launch(void* const* d_in, const int* in_sizes, int n_in,
                              void* d_out, int out_size) {
    const int*   src   = (const int*)  d_in[0];
    const int*   dst   = (const int*)  d_in[1];
    const float* x     = (const float*)d_in[2];
    const float* fc_w  = (const float*)d_in[3];
    const float* fc_b  = (const float*)d_in[4];
    const float* w1    = (const float*)d_in[5];
    const float* b1    = (const float*)d_in[6];
    const float* w2    = (const float*)d_in[7];
    const float* b2    = (const float*)d_in[8];
    const float* gamma = (const float*)d_in[9];
    const float* beta  = (const float*)d_in[10];
    float* out = (float*)d_out;

    const int GEMM_GRID = (N_NODES + 63) / 64;            // 1563
    const int SCAT_GRID = (N_EDGES * 16 + 255) / 256;     // 50000
    const int V4_GRID   = NH4 / 256;                      // 6250 (exact)

    zero_misc_kernel<<<(N_NODES + 255) / 256, 256>>>();
    degree_kernel<<<(N_EDGES + 255) / 256, 256>>>(src, dst);
    norm_kernel<<<(N_NODES + 255) / 256, 256>>>();

    fc_kernel<<<GEMM_GRID, 256>>>(x, fc_w, fc_b);

    // layer 1
    gemm64_kernel<<<GEMM_GRID, 256>>>(w1);
    zero_agg_kernel<<<V4_GRID, 256>>>();
    scatter_kernel<<<SCAT_GRID, 256>>>(src, dst);
    combine_kernel<<<V4_GRID, 256>>>(b1);

    // layer 2 (+ fused BN stats)
    gemm64_kernel<<<GEMM_GRID, 256>>>(w2);
    zero_agg_kernel<<<V4_GRID, 256>>>();
    scatter_kernel<<<SCAT_GRID, 256>>>(src, dst);
    combine2_bn_kernel<<<1184, 256>>>(b2);

    bn_finalize_kernel<<<1, 64>>>();
    bn_apply_kernel<<<V4_GRID, 256>>>(gamma, beta, out);
}

// round 5
// speedup vs baseline: 5.2605x; 1.2775x over previous
#include <cuda_runtime.h>
#include <math.h>

#define N_NODES 100000
#define N_EDGES 800000
#define IN_FEATS 128
#define HID 64
#define NH (N_NODES * HID)
#define NH4 (NH / 4)
#define SCALE 0.70710678118654752440f
#define BN_EPS 1e-5f

// ---------------- scratch (__device__ globals; no allocation allowed) -------
__device__ float g_h[NH];
__device__ float g_t[NH];                 // (h @ w) * norm_out, per layer
__device__ float g_norm_out[N_NODES];
__device__ float g_norm_in[N_NODES];
__device__ int   g_deg_out[N_NODES];
__device__ int   g_deg_in[N_NODES];
__device__ int   g_row_ptr[N_NODES + 1];  // CSR by dst
__device__ int   g_cursor[N_NODES];
__device__ int   g_csr_src[N_EDGES];
__device__ int   g_bsum[128];
__device__ int   g_boff[128];
__device__ float g_sum[HID];
__device__ float g_sumsq[HID];
__device__ float g_mu[HID];
__device__ float g_rstd[HID];

// ---------------- setup ------------------------------------------------------

__global__ void zero_misc_kernel() {
    int i = blockIdx.x * blockDim.x + threadIdx.x;
    if (i < N_NODES) { g_deg_out[i] = 0; g_deg_in[i] = 0; }
    if (i < HID)     { g_sum[i] = 0.f; g_sumsq[i] = 0.f; }
}

__global__ void degree_kernel(const int* __restrict__ src, const int* __restrict__ dst) {
    int e = blockIdx.x * blockDim.x + threadIdx.x;
    if (e >= N_EDGES) return;
    atomicAdd(&g_deg_out[src[e]], 1);
    atomicAdd(&g_deg_in[dst[e]], 1);
}

__global__ void norm_kernel() {
    int n = blockIdx.x * blockDim.x + threadIdx.x;
    if (n >= N_NODES) return;
    g_norm_out[n] = rsqrtf((float)max(g_deg_out[n], 1));
    g_norm_in[n]  = rsqrtf((float)max(g_deg_in[n], 1));
}

// ---- prefix scan of deg_in -> row_ptr (3 kernels) ----
__global__ void scan1_kernel() {
    __shared__ int swarp[32];
    int tid = threadIdx.x;
    int i = blockIdx.x * 1024 + tid;
    int v = (i < N_NODES) ? g_deg_in[i] : 0;
    int lane = tid & 31, w = tid >> 5;
    int x = v;
    #pragma unroll
    for (int d = 1; d < 32; d <<= 1) {
        int y = __shfl_up_sync(0xffffffffu, x, d);
        if (lane >= d) x += y;
    }
    if (lane == 31) swarp[w] = x;
    __syncthreads();
    if (w == 0) {
        int y = swarp[lane];
        #pragma unroll
        for (int d = 1; d < 32; d <<= 1) {
            int z = __shfl_up_sync(0xffffffffu, y, d);
            if (lane >= d) y += z;
        }
        swarp[lane] = y;
    }
    __syncthreads();
    int excl = x - v + (w > 0 ? swarp[w - 1] : 0);
    if (i < N_NODES) g_row_ptr[i] = excl;
    if (tid == 1023) g_bsum[blockIdx.x] = swarp[31];
}

__global__ void scan2_kernel(int nb) {
    __shared__ int swarp[4];
    int tid = threadIdx.x, lane = tid & 31, w = tid >> 5;
    int v = (tid < nb) ? g_bsum[tid] : 0;
    int x = v;
    #pragma unroll
    for (int d = 1; d < 32; d <<= 1) {
        int y = __shfl_up_sync(0xffffffffu, x, d);
        if (lane >= d) x += y;
    }
    if (lane == 31) swarp[w] = x;
    __syncthreads();
    if (w == 0 && lane < 4) {
        int y = swarp[lane];
        #pragma unroll
        for (int d = 1; d < 4; d <<= 1) {
            int z = __shfl_up_sync(0x0000000fu, y, d);
            if (lane >= d) y += z;
        }
        swarp[lane] = y;
    }
    __syncthreads();
    int excl = x - v + (w > 0 ? swarp[w - 1] : 0);
    if (tid < nb) g_boff[tid] = excl;
}

__global__ void scan3_kernel() {
    int i = blockIdx.x * blockDim.x + threadIdx.x;
    if (i < N_NODES) {
        int r = g_row_ptr[i] + g_boff[i >> 10];
        g_row_ptr[i] = r;
        g_cursor[i] = r;
    }
    if (i == 0) g_row_ptr[N_NODES] = N_EDGES;
}

__global__ void fill_csr_kernel(const int* __restrict__ src, const int* __restrict__ dst) {
    int e = blockIdx.x * blockDim.x + threadIdx.x;
    if (e >= N_EDGES) return;
    int p = atomicAdd(&g_cursor[dst[e]], 1);
    g_csr_src[p] = src[e];
}

// ---------------- fused fc + gemm(w1) -----------------------------------------
// 128x64 tile per 256-thread block, 8x4 accumulators per thread.
// Writes g_h = x@fc_w + fc_b   and   g_t = (g_h @ w1) * norm_out.
__global__ __launch_bounds__(256) void fc_fused_kernel(const float* __restrict__ x,
                                                       const float* __restrict__ fw,
                                                       const float* __restrict__ fb,
                                                       const float* __restrict__ w1) {
    __shared__ float xs[128][64];   // 32 KB (also reused to stage h)
    __shared__ float ws[64][64];    // 16 KB
    int tid = threadIdx.x;
    int row0 = blockIdx.x * 128;
    int tx = tid & 15;     // 4-col group
    int ty = tid >> 4;     // 8-row group
    int r0 = ty * 8;

    float4 acc[8];
    #pragma unroll
    for (int i = 0; i < 8; i++) acc[i] = make_float4(0.f, 0.f, 0.f, 0.f);

    for (int kc = 0; kc < IN_FEATS; kc += 64) {
        for (int i = tid; i < 1024; i += 256) {
            int k = i >> 4, j4 = i & 15;
            ((float4*)&ws[k][0])[j4] = ((const float4*)(fw + (size_t)(kc + k) * HID))[j4];
        }
        for (int i = tid; i < 2048; i += 256) {
            int r = i >> 4, k4 = i & 15;
            int node = row0 + r;
            float4 v = make_float4(0.f, 0.f, 0.f, 0.f);
            if (node < N_NODES) v = ((const float4*)(x + (size_t)node * IN_FEATS + kc))[k4];
            ((float4*)&xs[r][0])[k4] = v;
        }
        __syncthreads();
        #pragma unroll
        for (int k = 0; k < 64; k += 4) {
            float4 b0 = ((float4*)&ws[k + 0][0])[tx];
            float4 b1 = ((float4*)&ws[k + 1][0])[tx];
            float4 b2 = ((float4*)&ws[k + 2][0])[tx];
            float4 b3 = ((float4*)&ws[k + 3][0])[tx];
            #pragma unroll
            for (int i = 0; i < 8; i++) {
                float4 a = ((float4*)&xs[r0 + i][0])[k >> 2];
                acc[i].x = fmaf(a.x, b0.x, acc[i].x); acc[i].y = fmaf(a.x, b0.y, acc[i].y);
                acc[i].z = fmaf(a.x, b0.z, acc[i].z); acc[i].w = fmaf(a.x, b0.w, acc[i].w);
                acc[i].x = fmaf(a.y, b1.x, acc[i].x); acc[i].y = fmaf(a.y, b1.y, acc[i].y);
                acc[i].z = fmaf(a.y, b1.z, acc[i].z); acc[i].w = fmaf(a.y, b1.w, acc[i].w);
                acc[i].x = fmaf(a.z, b2.x, acc[i].x); acc[i].y = fmaf(a.z, b2.y, acc[i].y);
                acc[i].z = fmaf(a.z, b2.z, acc[i].z); acc[i].w = fmaf(a.z, b2.w, acc[i].w);
                acc[i].x = fmaf(a.w, b3.x, acc[i].x); acc[i].y = fmaf(a.w, b3.y, acc[i].y);
                acc[i].z = fmaf(a.w, b3.z, acc[i].z); acc[i].w = fmaf(a.w, b3.w, acc[i].w);
            }
        }
        __syncthreads();
    }

    // bias; write h; stage h into xs (smem) for second GEMM
    float4 bias = ((const float4*)fb)[tx];
    #pragma unroll
    for (int i = 0; i < 8; i++) {
        float4 o;
        o.x = acc[i].x + bias.x; o.y = acc[i].y + bias.y;
        o.z = acc[i].z + bias.z; o.w = acc[i].w + bias.w;
        int node = row0 + r0 + i;
        if (node < N_NODES) ((float4*)(g_h + (size_t)node * HID))[tx] = o;
        ((float4*)&xs[r0 + i][0])[tx] = o;
    }
    for (int i = tid; i < 1024; i += 256) {
        int k = i >> 4, j4 = i & 15;
        ((float4*)&ws[k][0])[j4] = ((const float4*)(w1 + (size_t)k * HID))[j4];
    }
    __syncthreads();

    float4 acc2[8];
    #pragma unroll
    for (int i = 0; i < 8; i++) acc2[i] = make_float4(0.f, 0.f, 0.f, 0.f);
    #pragma unroll
    for (int k = 0; k < 64; k += 4) {
        float4 b0 = ((float4*)&ws[k + 0][0])[tx];
        float4 b1 = ((float4*)&ws[k + 1][0])[tx];
        float4 b2 = ((float4*)&ws[k + 2][0])[tx];
        float4 b3 = ((float4*)&ws[k + 3][0])[tx];
        #pragma unroll
        for (int i = 0; i < 8; i++) {
            float4 a = ((float4*)&xs[r0 + i][0])[k >> 2];
            acc2[i].x = fmaf(a.x, b0.x, acc2[i].x); acc2[i].y = fmaf(a.x, b0.y, acc2[i].y);
            acc2[i].z = fmaf(a.x, b0.z, acc2[i].z); acc2[i].w = fmaf(a.x, b0.w, acc2[i].w);
            acc2[i].x = fmaf(a.y, b1.x, acc2[i].x); acc2[i].y = fmaf(a.y, b1.y, acc2[i].y);
            acc2[i].z = fmaf(a.y, b1.z, acc2[i].z); acc2[i].w = fmaf(a.y, b1.w, acc2[i].w);
            acc2[i].x = fmaf(a.z, b2.x, acc2[i].x); acc2[i].y = fmaf(a.z, b2.y, acc2[i].y);
            acc2[i].z = fmaf(a.z, b2.z, acc2[i].z); acc2[i].w = fmaf(a.z, b2.w, acc2[i].w);
            acc2[i].x = fmaf(a.w, b3.x, acc2[i].x); acc2[i].y = fmaf(a.w, b3.y, acc2[i].y);
            acc2[i].z = fmaf(a.w, b3.z, acc2[i].z); acc2[i].w = fmaf(a.w, b3.w, acc2[i].w);
        }
    }
    #pragma unroll
    for (int i = 0; i < 8; i++) {
        int node = row0 + r0 + i;
        if (node < N_NODES) {
            float no = g_norm_out[node];
            float4 o = make_float4(acc2[i].x * no, acc2[i].y * no,
                                   acc2[i].z * no, acc2[i].w * no);
            ((float4*)(g_t + (size_t)node * HID))[tx] = o;
        }
    }
}

// ---------------- gemm for layer 2: g_t = (g_h @ w2) * norm_out ----------------
__global__ __launch_bounds__(256) void gemm2_kernel(const float* __restrict__ w) {
    __shared__ float xs[128][64];
    __shared__ float ws[64][64];
    int tid = threadIdx.x;
    int row0 = blockIdx.x * 128;
    int tx = tid & 15;
    int ty = tid >> 4;
    int r0 = ty * 8;

    for (int i = tid; i < 1024; i += 256) {
        int k = i >> 4, j4 = i & 15;
        ((float4*)&ws[k][0])[j4] = ((const float4*)(w + (size_t)k * HID))[j4];
    }
    for (int i = tid; i < 2048; i += 256) {
        int r = i >> 4, k4 = i & 15;
        int node = row0 + r;
        float4 v = make_float4(0.f, 0.f, 0.f, 0.f);
        if (node < N_NODES) v = ((const float4*)(g_h + (size_t)node * HID))[k4];
        ((float4*)&xs[r][0])[k4] = v;
    }
    __syncthreads();

    float4 acc[8];
    #pragma unroll
    for (int i = 0; i < 8; i++) acc[i] = make_float4(0.f, 0.f, 0.f, 0.f);
    #pragma unroll
    for (int k = 0; k < 64; k += 4) {
        float4 b0 = ((float4*)&ws[k + 0][0])[tx];
        float4 b1 = ((float4*)&ws[k + 1][0])[tx];
        float4 b2 = ((float4*)&ws[k + 2][0])[tx];
        float4 b3 = ((float4*)&ws[k + 3][0])[tx];
        #pragma unroll
        for (int i = 0; i < 8; i++) {
            float4 a = ((float4*)&xs[r0 + i][0])[k >> 2];
            acc[i].x = fmaf(a.x, b0.x, acc[i].x); acc[i].y = fmaf(a.x, b0.y, acc[i].y);
            acc[i].z = fmaf(a.x, b0.z, acc[i].z); acc[i].w = fmaf(a.x, b0.w, acc[i].w);
            acc[i].x = fmaf(a.y, b1.x, acc[i].x); acc[i].y = fmaf(a.y, b1.y, acc[i].y);
            acc[i].z = fmaf(a.y, b1.z, acc[i].z); acc[i].w = fmaf(a.y, b1.w, acc[i].w);
            acc[i].x = fmaf(a.z, b2.x, acc[i].x); acc[i].y = fmaf(a.z, b2.y, acc[i].y);
            acc[i].z = fmaf(a.z, b2.z, acc[i].z); acc[i].w = fmaf(a.z, b2.w, acc[i].w);
            acc[i].x = fmaf(a.w, b3.x, acc[i].x); acc[i].y = fmaf(a.w, b3.y, acc[i].y);
            acc[i].z = fmaf(a.w, b3.z, acc[i].z); acc[i].w = fmaf(a.w, b3.w, acc[i].w);
        }
    }
    #pragma unroll
    for (int i = 0; i < 8; i++) {
        int node = row0 + r0 + i;
        if (node < N_NODES) {
            float no = g_norm_out[node];
            float4 o = make_float4(acc[i].x * no, acc[i].y * no,
                                   acc[i].z * no, acc[i].w * no);
            ((float4*)(g_t + (size_t)node * HID))[tx] = o;
        }
    }
}

// ---------------- gather-aggregate + combine (no atomics) ----------------------
// 16 lanes per dst node; each lane owns one float4 feature group.
// h[n] = (h[n] + (sum_{e in in(n)} t[src_e]) * norm_in[n] + b) * SCALE
__global__ __launch_bounds__(256) void agg_combine_kernel(const float* __restrict__ b) {
    int gt = blockIdx.x * 256 + threadIdx.x;
    int node = gt >> 4;
    if (node >= N_NODES) return;
    int lane = gt & 15;
    int beg = g_row_ptr[node];
    int end = g_row_ptr[node + 1];
    float4 acc = make_float4(0.f, 0.f, 0.f, 0.f);
    for (int e = beg; e < end; e++) {
        int s = g_csr_src[e];
        float4 v = ((const float4*)g_t)[(size_t)s * 16 + lane];
        acc.x += v.x; acc.y += v.y; acc.z += v.z; acc.w += v.w;
    }
    float ni = g_norm_in[node];
    float4 bb = ((const float4*)b)[lane];
    size_t idx = (size_t)node * 16 + lane;
    float4 h = ((float4*)g_h)[idx];
    h.x = (h.x + acc.x * ni + bb.x) * SCALE;
    h.y = (h.y + acc.y * ni + bb.y) * SCALE;
    h.z = (h.z + acc.z * ni + bb.z) * SCALE;
    h.w = (h.w + acc.w * ni + bb.w) * SCALE;
    ((float4*)g_h)[idx] = h;
}

// layer-2 variant fused with BN statistics (grid-stride; lane fixed per thread)
__global__ __launch_bounds__(256) void agg_combine2_bn_kernel(const float* __restrict__ b) {
    __shared__ float ssum[HID];
    __shared__ float ssq[HID];
    int tid = threadIdx.x;
    if (tid < HID) { ssum[tid] = 0.f; ssq[tid] = 0.f; }
    __syncthreads();

    int lane = tid & 15;
    float4 bb = ((const float4*)b)[lane];
    float4 s4 = make_float4(0.f, 0.f, 0.f, 0.f);
    float4 q4 = make_float4(0.f, 0.f, 0.f, 0.f);
    int stride = gridDim.x * 256;               // multiple of 16
    for (int gt = blockIdx.x * 256 + tid; gt < N_NODES * 16; gt += stride) {
        int node = gt >> 4;
        int beg = g_row_ptr[node];
        int end = g_row_ptr[node + 1];
        float4 acc = make_float4(0.f, 0.f, 0.f, 0.f);
        for (int e = beg; e < end; e++) {
            int s = g_csr_src[e];
            float4 v = ((const float4*)g_t)[(size_t)s * 16 + lane];
            acc.x += v.x; acc.y += v.y; acc.z += v.z; acc.w += v.w;
        }
        float ni = g_norm_in[node];
        size_t idx = (size_t)node * 16 + lane;
        float4 h = ((float4*)g_h)[idx];
        h.x = (h.x + acc.x * ni + bb.x) * SCALE;
        h.y = (h.y + acc.y * ni + bb.y) * SCALE;
        h.z = (h.z + acc.z * ni + bb.z) * SCALE;
        h.w = (h.w + acc.w * ni + bb.w) * SCALE;
        ((float4*)g_h)[idx] = h;
        s4.x += h.x; s4.y += h.y; s4.z += h.z; s4.w += h.w;
        q4.x = fmaf(h.x, h.x, q4.x); q4.y = fmaf(h.y, h.y, q4.y);
        q4.z = fmaf(h.z, h.z, q4.z); q4.w = fmaf(h.w, h.w, q4.w);
    }
    int f = lane * 4;
    atomicAdd(&ssum[f + 0], s4.x); atomicAdd(&ssum[f + 1], s4.y);
    atomicAdd(&ssum[f + 2], s4.z); atomicAdd(&ssum[f + 3], s4.w);
    atomicAdd(&ssq[f + 0], q4.x); atomicAdd(&ssq[f + 1], q4.y);
    atomicAdd(&ssq[f + 2], q4.z); atomicAdd(&ssq[f + 3], q4.w);
    __syncthreads();
    if (tid < HID) {
        atomicAdd(&g_sum[tid], ssum[tid]);
        atomicAdd(&g_sumsq[tid], ssq[tid]);
    }
}

__global__ void bn_finalize_kernel() {
    int j = threadIdx.x;
    if (j < HID) {
        float mu = g_sum[j] / (float)N_NODES;
        float var = g_sumsq[j] / (float)N_NODES - mu * mu;
        g_mu[j] = mu;
        g_rstd[j] = rsqrtf(var + BN_EPS);
    }
}

__global__ void bn_apply_kernel(const float* __restrict__ gamma,
                                const float* __restrict__ beta,
                                float* __restrict__ out) {
    int i = blockIdx.x * blockDim.x + threadIdx.x;
    if (i >= NH4) return;
    int j4 = i & 15;
    float4 h  = ((float4*)g_h)[i];
    float4 mu = ((float4*)g_mu)[j4];
    float4 rs = ((float4*)g_rstd)[j4];
    float4 ga = ((const float4*)gamma)[j4];
    float4 be = ((const float4*)beta)[j4];
    float4 o;
    o.x = (h.x - mu.x) * rs.x * ga.x + be.x;
    o.y = (h.y - mu.y) * rs.y * ga.y + be.y;
    o.z = (h.z - mu.z) * rs.z * ga.z + be.z;
    o.w = (h.w - mu.w) * rs.w * ga.w + be.w;
    ((float4*)out)[i] = o;
}

// ---------------- launch ------------------------------------------------------
extern "C" void kernel_launch(void* const* d_in, const int* in_sizes, int n_in,
                              void* d_out, int out_size) {
    const int*   src   = (const int*)  d_in[0];
    const int*   dst   = (const int*)  d_in[1];
    const float* x     = (const float*)d_in[2];
    const float* fc_w  = (const float*)d_in[3];
    const float* fc_b  = (const float*)d_in[4];
    const float* w1    = (const float*)d_in[5];
    const float* b1    = (const float*)d_in[6];
    const float* w2    = (const float*)d_in[7];
    const float* b2    = (const float*)d_in[8];
    const float* gamma = (const float*)d_in[9];
    const float* beta  = (const float*)d_in[10];
    float* out = (float*)d_out;

    const int SCAN_NB   = (N_NODES + 1023) / 1024;        // 98
    const int GEMM_GRID = (N_NODES + 127) / 128;          // 782
    const int AGG_GRID  = (N_NODES * 16 + 255) / 256;     // 6250
    const int V4_GRID   = NH4 / 256;                      // 6250 (exact)

    // degrees, norms, CSR-by-dst
    zero_misc_kernel<<<(N_NODES + 255) / 256, 256>>>();
    degree_kernel<<<(N_EDGES + 255) / 256, 256>>>(src, dst);
    norm_kernel<<<(N_NODES + 255) / 256, 256>>>();
    scan1_kernel<<<SCAN_NB, 1024>>>();
    scan2_kernel<<<1, 128>>>(SCAN_NB);
    scan3_kernel<<<(N_NODES + 255) / 256, 256>>>();
    fill_csr_kernel<<<(N_EDGES + 255) / 256, 256>>>(src, dst);

    // fc + layer-1 gemm (fused), then gather-aggregate + combine
    fc_fused_kernel<<<GEMM_GRID, 256>>>(x, fc_w, fc_b, w1);
    agg_combine_kernel<<<AGG_GRID, 256>>>(b1);

    // layer 2
    gemm2_kernel<<<GEMM_GRID, 256>>>(w2);
    agg_combine2_bn_kernel<<<1184, 256>>>(b2);

    // batchnorm
    bn_finalize_kernel<<<1, 64>>>();
    bn_apply_kernel<<<V4_GRID, 256>>>(gamma, beta, out);
}

// round 7
// speedup vs baseline: 5.5480x; 1.0547x over previous
#include <cuda_runtime.h>
#include <math.h>

#define N_NODES 100000
#define N_EDGES 800000
#define IN_FEATS 128
#define HID 64
#define NH (N_NODES * HID)
#define NH4 (NH / 4)
#define SCALE 0.70710678118654752440f
#define BN_EPS 1e-5f

typedef unsigned long long u64;

// ---------------- f32x2 helpers (Blackwell packed fp32) ----------------------
__device__ __forceinline__ u64 pack2(float a) {
    unsigned u = __float_as_uint(a);
    u64 r;
    asm("mov.b64 %0, {%1, %1};" : "=l"(r) : "r"(u));
    return r;
}
__device__ __forceinline__ u64 ffma2(u64 a, u64 b, u64 c) {
    u64 d;
    asm("fma.rn.f32x2 %0, %1, %2, %3;" : "=l"(d) : "l"(a), "l"(b), "l"(c));
    return d;
}
__device__ __forceinline__ float2 unpack2(u64 v) {
    float2 f;
    asm("mov.b64 {%0, %1}, %2;" : "=f"(f.x), "=f"(f.y) : "l"(v));
    return f;
}

// ---------------- scratch (__device__ globals; no allocation allowed) -------
__device__ float g_h[NH];
__device__ float g_t[NH];                 // (h @ w) * norm_out, per layer
__device__ float g_norm_out[N_NODES];
__device__ float g_norm_in[N_NODES];
__device__ int   g_deg_out[N_NODES];
__device__ int   g_deg_in[N_NODES];
__device__ int   g_row_ptr[N_NODES + 1];  // CSR by dst
__device__ int   g_cursor[N_NODES];
__device__ int   g_csr_src[N_EDGES];
__device__ int   g_bsum[128];
__device__ int   g_boff[128];
__device__ float g_sum[HID];
__device__ float g_sumsq[HID];
__device__ float g_mu[HID];
__device__ float g_rstd[HID];

// ---------------- setup ------------------------------------------------------

__global__ void zero_misc_kernel() {
    int i = blockIdx.x * blockDim.x + threadIdx.x;
    if (i < N_NODES) { g_deg_out[i] = 0; g_deg_in[i] = 0; }
    if (i < HID)     { g_sum[i] = 0.f; g_sumsq[i] = 0.f; }
}

__global__ void degree_kernel(const int* __restrict__ src, const int* __restrict__ dst) {
    int e = blockIdx.x * blockDim.x + threadIdx.x;
    if (e >= N_EDGES) return;
    atomicAdd(&g_deg_out[src[e]], 1);
    atomicAdd(&g_deg_in[dst[e]], 1);
}

__global__ void norm_kernel() {
    int n = blockIdx.x * blockDim.x + threadIdx.x;
    if (n >= N_NODES) return;
    g_norm_out[n] = rsqrtf((float)max(g_deg_out[n], 1));
    g_norm_in[n]  = rsqrtf((float)max(g_deg_in[n], 1));
}

// ---- prefix scan of deg_in -> row_ptr (3 kernels) ----
__global__ void scan1_kernel() {
    __shared__ int swarp[32];
    int tid = threadIdx.x;
    int i = blockIdx.x * 1024 + tid;
    int v = (i < N_NODES) ? g_deg_in[i] : 0;
    int lane = tid & 31, w = tid >> 5;
    int x = v;
    #pragma unroll
    for (int d = 1; d < 32; d <<= 1) {
        int y = __shfl_up_sync(0xffffffffu, x, d);
        if (lane >= d) x += y;
    }
    if (lane == 31) swarp[w] = x;
    __syncthreads();
    if (w == 0) {
        int y = swarp[lane];
        #pragma unroll
        for (int d = 1; d < 32; d <<= 1) {
            int z = __shfl_up_sync(0xffffffffu, y, d);
            if (lane >= d) y += z;
        }
        swarp[lane] = y;
    }
    __syncthreads();
    int excl = x - v + (w > 0 ? swarp[w - 1] : 0);
    if (i < N_NODES) g_row_ptr[i] = excl;
    if (tid == 1023) g_bsum[blockIdx.x] = swarp[31];
}

__global__ void scan2_kernel(int nb) {
    __shared__ int swarp[4];
    int tid = threadIdx.x, lane = tid & 31, w = tid >> 5;
    int v = (tid < nb) ? g_bsum[tid] : 0;
    int x = v;
    #pragma unroll
    for (int d = 1; d < 32; d <<= 1) {
        int y = __shfl_up_sync(0xffffffffu, x, d);
        if (lane >= d) x += y;
    }
    if (lane == 31) swarp[w] = x;
    __syncthreads();
    if (w == 0 && lane < 4) {
        int y = swarp[lane];
        #pragma unroll
        for (int d = 1; d < 4; d <<= 1) {
            int z = __shfl_up_sync(0x0000000fu, y, d);
            if (lane >= d) y += z;
        }
        swarp[lane] = y;
    }
    __syncthreads();
    int excl = x - v + (w > 0 ? swarp[w - 1] : 0);
    if (tid < nb) g_boff[tid] = excl;
}

__global__ void scan3_kernel() {
    int i = blockIdx.x * blockDim.x + threadIdx.x;
    if (i < N_NODES) {
        int r = g_row_ptr[i] + g_boff[i >> 10];
        g_row_ptr[i] = r;
        g_cursor[i] = r;
    }
    if (i == 0) g_row_ptr[N_NODES] = N_EDGES;
}

__global__ void fill_csr_kernel(const int* __restrict__ src, const int* __restrict__ dst) {
    int e = blockIdx.x * blockDim.x + threadIdx.x;
    if (e >= N_EDGES) return;
    int p = atomicAdd(&g_cursor[dst[e]], 1);
    g_csr_src[p] = src[e];
}

// ---------------- fused fc + gemm(w1), f32x2 mainloop --------------------------
// 128x64 tile per 256-thread block, 8 rows x 4 cols per thread (2 f32x2 accs/row).
// Writes g_h = x@fc_w + fc_b   and   g_t = (g_h @ w1) * norm_out.
__global__ __launch_bounds__(256) void fc_fused_kernel(const float* __restrict__ x,
                                                       const float* __restrict__ fw,
                                                       const float* __restrict__ fb,
                                                       const float* __restrict__ w1) {
    __shared__ float xs[128][64];   // 32 KB (also reused to stage h)
    __shared__ float ws[64][64];    // 16 KB
    int tid = threadIdx.x;
    int row0 = blockIdx.x * 128;
    int tx = tid & 15;     // 4-col group
    int ty = tid >> 4;     // 8-row group
    int r0 = ty * 8;

    u64 accL[8], accH[8];
    #pragma unroll
    for (int i = 0; i < 8; i++) { accL[i] = 0ull; accH[i] = 0ull; }

    for (int kc = 0; kc < IN_FEATS; kc += 64) {
        for (int i = tid; i < 1024; i += 256) {
            int k = i >> 4, j4 = i & 15;
            ((float4*)&ws[k][0])[j4] = ((const float4*)(fw + (size_t)(kc + k) * HID))[j4];
        }
        for (int i = tid; i < 2048; i += 256) {
            int r = i >> 4, k4 = i & 15;
            int node = row0 + r;
            float4 v = make_float4(0.f, 0.f, 0.f, 0.f);
            if (node < N_NODES) v = ((const float4*)(x + (size_t)node * IN_FEATS + kc))[k4];
            ((float4*)&xs[r][0])[k4] = v;
        }
        __syncthreads();
        #pragma unroll
        for (int k = 0; k < 64; k += 4) {
            float4 a[8];
            #pragma unroll
            for (int i = 0; i < 8; i++) a[i] = ((float4*)&xs[r0 + i][0])[k >> 2];
            #pragma unroll
            for (int s = 0; s < 4; s++) {
                const float* wp = &ws[k + s][tx * 4];
                u64 bL = *(const u64*)(wp);
                u64 bH = *(const u64*)(wp + 2);
                #pragma unroll
                for (int i = 0; i < 8; i++) {
                    float as = (s == 0) ? a[i].x : (s == 1) ? a[i].y : (s == 2) ? a[i].z : a[i].w;
                    u64 ap = pack2(as);
                    accL[i] = ffma2(ap, bL, accL[i]);
                    accH[i] = ffma2(ap, bH, accH[i]);
                }
            }
        }
        __syncthreads();
    }

    // bias; write h; stage h into xs (smem) for second GEMM
    float4 bias = ((const float4*)fb)[tx];
    #pragma unroll
    for (int i = 0; i < 8; i++) {
        float2 lo = unpack2(accL[i]);
        float2 hi = unpack2(accH[i]);
        float4 o;
        o.x = lo.x + bias.x; o.y = lo.y + bias.y;
        o.z = hi.x + bias.z; o.w = hi.y + bias.w;
        int node = row0 + r0 + i;
        if (node < N_NODES) ((float4*)(g_h + (size_t)node * HID))[tx] = o;
        ((float4*)&xs[r0 + i][0])[tx] = o;
        accL[i] = 0ull; accH[i] = 0ull;
    }
    for (int i = tid; i < 1024; i += 256) {
        int k = i >> 4, j4 = i & 15;
        ((float4*)&ws[k][0])[j4] = ((const float4*)(w1 + (size_t)k * HID))[j4];
    }
    __syncthreads();

    #pragma unroll
    for (int k = 0; k < 64; k += 4) {
        float4 a[8];
        #pragma unroll
        for (int i = 0; i < 8; i++) a[i] = ((float4*)&xs[r0 + i][0])[k >> 2];
        #pragma unroll
        for (int s = 0; s < 4; s++) {
            const float* wp = &ws[k + s][tx * 4];
            u64 bL = *(const u64*)(wp);
            u64 bH = *(const u64*)(wp + 2);
            #pragma unroll
            for (int i = 0; i < 8; i++) {
                float as = (s == 0) ? a[i].x : (s == 1) ? a[i].y : (s == 2) ? a[i].z : a[i].w;
                u64 ap = pack2(as);
                accL[i] = ffma2(ap, bL, accL[i]);
                accH[i] = ffma2(ap, bH, accH[i]);
            }
        }
    }
    #pragma unroll
    for (int i = 0; i < 8; i++) {
        int node = row0 + r0 + i;
        if (node < N_NODES) {
            float no = g_norm_out[node];
            float2 lo = unpack2(accL[i]);
            float2 hi = unpack2(accH[i]);
            float4 o = make_float4(lo.x * no, lo.y * no, hi.x * no, hi.y * no);
            ((float4*)(g_t + (size_t)node * HID))[tx] = o;
        }
    }
}

// ---------------- gemm for layer 2: g_t = (g_h @ w2) * norm_out ----------------
__global__ __launch_bounds__(256) void gemm2_kernel(const float* __restrict__ w) {
    __shared__ float xs[128][64];
    __shared__ float ws[64][64];
    int tid = threadIdx.x;
    int row0 = blockIdx.x * 128;
    int tx = tid & 15;
    int ty = tid >> 4;
    int r0 = ty * 8;

    for (int i = tid; i < 1024; i += 256) {
        int k = i >> 4, j4 = i & 15;
        ((float4*)&ws[k][0])[j4] = ((const float4*)(w + (size_t)k * HID))[j4];
    }
    for (int i = tid; i < 2048; i += 256) {
        int r = i >> 4, k4 = i & 15;
        int node = row0 + r;
        float4 v = make_float4(0.f, 0.f, 0.f, 0.f);
        if (node < N_NODES) v = ((const float4*)(g_h + (size_t)node * HID))[k4];
        ((float4*)&xs[r][0])[k4] = v;
    }
    __syncthreads();

    u64 accL[8], accH[8];
    #pragma unroll
    for (int i = 0; i < 8; i++) { accL[i] = 0ull; accH[i] = 0ull; }

    #pragma unroll
    for (int k = 0; k < 64; k += 4) {
        float4 a[8];
        #pragma unroll
        for (int i = 0; i < 8; i++) a[i] = ((float4*)&xs[r0 + i][0])[k >> 2];
        #pragma unroll
        for (int s = 0; s < 4; s++) {
            const float* wp = &ws[k + s][tx * 4];
            u64 bL = *(const u64*)(wp);
            u64 bH = *(const u64*)(wp + 2);
            #pragma unroll
            for (int i = 0; i < 8; i++) {
                float as = (s == 0) ? a[i].x : (s == 1) ? a[i].y : (s == 2) ? a[i].z : a[i].w;
                u64 ap = pack2(as);
                accL[i] = ffma2(ap, bL, accL[i]);
                accH[i] = ffma2(ap, bH, accH[i]);
            }
        }
    }
    #pragma unroll
    for (int i = 0; i < 8; i++) {
        int node = row0 + r0 + i;
        if (node < N_NODES) {
            float no = g_norm_out[node];
            float2 lo = unpack2(accL[i]);
            float2 hi = unpack2(accH[i]);
            float4 o = make_float4(lo.x * no, lo.y * no, hi.x * no, hi.y * no);
            ((float4*)(g_t + (size_t)node * HID))[tx] = o;
        }
    }
}

// ---------------- gather-aggregate + combine (no atomics) ----------------------
__global__ __launch_bounds__(256) void agg_combine_kernel(const float* __restrict__ b) {
    int gt = blockIdx.x * 256 + threadIdx.x;
    int node = gt >> 4;
    if (node >= N_NODES) return;
    int lane = gt & 15;
    int beg = g_row_ptr[node];
    int end = g_row_ptr[node + 1];
    float4 acc = make_float4(0.f, 0.f, 0.f, 0.f);
    for (int e = beg; e < end; e++) {
        int s = g_csr_src[e];
        float4 v = ((const float4*)g_t)[(size_t)s * 16 + lane];
        acc.x += v.x; acc.y += v.y; acc.z += v.z; acc.w += v.w;
    }
    float ni = g_norm_in[node];
    float4 bb = ((const float4*)b)[lane];
    size_t idx = (size_t)node * 16 + lane;
    float4 h = ((float4*)g_h)[idx];
    h.x = (h.x + acc.x * ni + bb.x) * SCALE;
    h.y = (h.y + acc.y * ni + bb.y) * SCALE;
    h.z = (h.z + acc.z * ni + bb.z) * SCALE;
    h.w = (h.w + acc.w * ni + bb.w) * SCALE;
    ((float4*)g_h)[idx] = h;
}

// layer-2 variant fused with BN statistics (grid-stride; lane fixed per thread)
__global__ __launch_bounds__(256) void agg_combine2_bn_kernel(const float* __restrict__ b) {
    __shared__ float ssum[HID];
    __shared__ float ssq[HID];
    int tid = threadIdx.x;
    if (tid < HID) { ssum[tid] = 0.f; ssq[tid] = 0.f; }
    __syncthreads();

    int lane = tid & 15;
    float4 bb = ((const float4*)b)[lane];
    float4 s4 = make_float4(0.f, 0.f, 0.f, 0.f);
    float4 q4 = make_float4(0.f, 0.f, 0.f, 0.f);
    int stride = gridDim.x * 256;               // multiple of 16
    for (int gt = blockIdx.x * 256 + tid; gt < N_NODES * 16; gt += stride) {
        int node = gt >> 4;
        int beg = g_row_ptr[node];
        int end = g_row_ptr[node + 1];
        float4 acc = make_float4(0.f, 0.f, 0.f, 0.f);
        for (int e = beg; e < end; e++) {
            int s = g_csr_src[e];
            float4 v = ((const float4*)g_t)[(size_t)s * 16 + lane];
            acc.x += v.x; acc.y += v.y; acc.z += v.z; acc.w += v.w;
        }
        float ni = g_norm_in[node];
        size_t idx = (size_t)node * 16 + lane;
        float4 h = ((float4*)g_h)[idx];
        h.x = (h.x + acc.x * ni + bb.x) * SCALE;
        h.y = (h.y + acc.y * ni + bb.y) * SCALE;
        h.z = (h.z + acc.z * ni + bb.z) * SCALE;
        h.w = (h.w + acc.w * ni + bb.w) * SCALE;
        ((float4*)g_h)[idx] = h;
        s4.x += h.x; s4.y += h.y; s4.z += h.z; s4.w += h.w;
        q4.x = fmaf(h.x, h.x, q4.x); q4.y = fmaf(h.y, h.y, q4.y);
        q4.z = fmaf(h.z, h.z, q4.z); q4.w = fmaf(h.w, h.w, q4.w);
    }
    int f = lane * 4;
    atomicAdd(&ssum[f + 0], s4.x); atomicAdd(&ssum[f + 1], s4.y);
    atomicAdd(&ssum[f + 2], s4.z); atomicAdd(&ssum[f + 3], s4.w);
    atomicAdd(&ssq[f + 0], q4.x); atomicAdd(&ssq[f + 1], q4.y);
    atomicAdd(&ssq[f + 2], q4.z); atomicAdd(&ssq[f + 3], q4.w);
    __syncthreads();
    if (tid < HID) {
        atomicAdd(&g_sum[tid], ssum[tid]);
        atomicAdd(&g_sumsq[tid], ssq[tid]);
    }
}

__global__ void bn_finalize_kernel() {
    int j = threadIdx.x;
    if (j < HID) {
        float mu = g_sum[j] / (float)N_NODES;
        float var = g_sumsq[j] / (float)N_NODES - mu * mu;
        g_mu[j] = mu;
        g_rstd[j] = rsqrtf(var + BN_EPS);
    }
}

__global__ void bn_apply_kernel(const float* __restrict__ gamma,
                                const float* __restrict__ beta,
                                float* __restrict__ out) {
    int i = blockIdx.x * blockDim.x + threadIdx.x;
    if (i >= NH4) return;
    int j4 = i & 15;
    float4 h  = ((float4*)g_h)[i];
    float4 mu = ((float4*)g_mu)[j4];
    float4 rs = ((float4*)g_rstd)[j4];
    float4 ga = ((const float4*)gamma)[j4];
    float4 be = ((const float4*)beta)[j4];
    float4 o;
    o.x = (h.x - mu.x) * rs.x * ga.x + be.x;
    o.y = (h.y - mu.y) * rs.y * ga.y + be.y;
    o.z = (h.z - mu.z) * rs.z * ga.z + be.z;
    o.w = (h.w - mu.w) * rs.w * ga.w + be.w;
    ((float4*)out)[i] = o;
}

// ---------------- launch ------------------------------------------------------
extern "C" void kernel_launch(void* const* d_in, const int* in_sizes, int n_in,
                              void* d_out, int out_size) {
    const int*   src   = (const int*)  d_in[0];
    const int*   dst   = (const int*)  d_in[1];
    const float* x     = (const float*)d_in[2];
    const float* fc_w  = (const float*)d_in[3];
    const float* fc_b  = (const float*)d_in[4];
    const float* w1    = (const float*)d_in[5];
    const float* b1    = (const float*)d_in[6];
    const float* w2    = (const float*)d_in[7];
    const float* b2    = (const float*)d_in[8];
    const float* gamma = (const float*)d_in[9];
    const float* beta  = (const float*)d_in[10];
    float* out = (float*)d_out;

    const int SCAN_NB   = (N_NODES + 1023) / 1024;        // 98
    const int GEMM_GRID = (N_NODES + 127) / 128;          // 782
    const int AGG_GRID  = (N_NODES * 16 + 255) / 256;     // 6250
    const int V4_GRID   = NH4 / 256;                      // 6250 (exact)

    // degrees, norms, CSR-by-dst
    zero_misc_kernel<<<(N_NODES + 255) / 256, 256>>>();
    degree_kernel<<<(N_EDGES + 255) / 256, 256>>>(src, dst);
    norm_kernel<<<(N_NODES + 255) / 256, 256>>>();
    scan1_kernel<<<SCAN_NB, 1024>>>();
    scan2_kernel<<<1, 128>>>(SCAN_NB);
    scan3_kernel<<<(N_NODES + 255) / 256, 256>>>();
    fill_csr_kernel<<<(N_EDGES + 255) / 256, 256>>>(src, dst);

    // fc + layer-1 gemm (fused), then gather-aggregate + combine
    fc_fused_kernel<<<GEMM_GRID, 256>>>(x, fc_w, fc_b, w1);
    agg_combine_kernel<<<AGG_GRID, 256>>>(b1);

    // layer 2
    gemm2_kernel<<<GEMM_GRID, 256>>>(w2);
    agg_combine2_bn_kernel<<<1184, 256>>>(b2);

    // batchnorm
    bn_finalize_kernel<<<1, 64>>>();
    bn_apply_kernel<<<V4_GRID, 256>>>(gamma, beta, out);
}